// round 12
// baseline (speedup 1.0000x reference)
#include <cuda_runtime.h>
#include <cstdint>

#define CIN  128
#define NHW  128
#define C1   50
#define C2   18
#define BATCH 8
#define HH   512
#define WW   512

typedef unsigned long long ull;

// scratch (allocation-free rule: device globals)
__device__ float g_h[BATCH * C1 * NHW * NHW];       // conv1 output (26.2 MB)
__device__ float g_cond[BATCH * C2 * NHW * NHW];    // conv2 output (9.4 MB)
__device__ __align__(16) float2 g_wdup[CIN * 9 * C1];  // conv1 weights, duplicated (w,w), chunk-contiguous

__device__ __forceinline__ ull pk2(float lo, float hi) {
    ull r;
    asm("mov.b64 %0, {%1, %2};" : "=l"(r) : "f"(lo), "f"(hi));
    return r;
}
__device__ __forceinline__ void upk2(ull v, float& lo, float& hi) {
    asm("mov.b64 {%0, %1}, %2;" : "=f"(lo), "=f"(hi) : "l"(v));
}
__device__ __forceinline__ void fma2(ull& d, ull a, ull b) {
    asm("fma.rn.f32x2 %0, %1, %2, %3;" : "=l"(d) : "l"(a), "l"(b), "l"(d));
}
__device__ __forceinline__ uint32_t smem_u32(const void* p) {
    uint32_t a;
    asm("{ .reg .u64 t; cvta.to.shared.u64 t, %1; cvt.u32.u64 %0, t; }"
        : "=r"(a) : "l"(p));
    return a;
}
__device__ __forceinline__ void cp16(uint32_t dst, const void* src, int sz) {
    asm volatile("cp.async.cg.shared.global [%0], [%1], 16, %2;"
                 :: "r"(dst), "l"(src), "r"(sz) : "memory");
}
__device__ __forceinline__ void cp_commit() {
    asm volatile("cp.async.commit_group;" ::: "memory");
}
__device__ __forceinline__ void cp_wait1() {
    asm volatile("cp.async.wait_group 1;" ::: "memory");
}

// ---------------------------------------------------------------------------
// setup: duplicate conv1 weights into (w,w) float2, layout [cin][kk][oc]
// so conv1's per-chunk weight staging is a contiguous 16B cp.async stream.
// ---------------------------------------------------------------------------
__global__ void setup_w1_kernel(const float* __restrict__ w1)
{
    int i = blockIdx.x * 256 + threadIdx.x;       // 128*9*50 = 57600
    if (i < CIN * 9 * C1) {
        int cin = i / (9 * C1);
        int rem = i - cin * (9 * C1);
        int kk  = rem / C1;
        int oc  = rem - kk * C1;
        float w = w1[oc * (CIN * 9) + cin * 9 + kk];
        g_wdup[i] = make_float2(w, w);
    }
}

// conv1 smem layout (dynamic):
//   s_raw: [2][8][10][40] float  = 25600 B  (raw input rows, 4-col halo pad each side)
//   s_w:   [2][8][9][50] float2  = 57600 B  (weights duplicated (w,w))
#define C1_RAW_FLOATS (8 * 10 * 40)     // per buffer: 3200
#define C1_W_F2       (8 * 9 * 50)      // per buffer: 3600
#define C1_SMEM_BYTES (2 * C1_RAW_FLOATS * 4 + 2 * C1_W_F2 * 8)   // 83200

// stage one 8-channel chunk via cp.async (input rows + weights)
__device__ __forceinline__ void c1_stage(const float* __restrict__ ctrl_chunk,
                                         const float4* __restrict__ wsrc,
                                         int y0, int x0, int tid,
                                         uint32_t raw_dst, uint32_t w_dst)
{
    // input: 8c x 10r x 10 groups of 16B = 800 ops
#pragma unroll
    for (int it = 0; it < 4; ++it) {
        int idx = tid + it * 256;
        if (idx < 800) {
            int c = idx / 100, rem = idx - c * 100;
            int r = rem / 10, g = rem - r * 10;
            int y = y0 + r - 1;
            int gx = x0 - 4 + g * 4;
            bool ok = ((unsigned)y < (unsigned)NHW) && ((unsigned)gx <= 124u);
            int soff = ok ? (c * (NHW * NHW) + y * NHW + gx) : 0;
            cp16(raw_dst + ((c * 10 + r) * 40 + g * 4) * 4,
                 ctrl_chunk + soff, ok ? 16 : 0);
        }
    }
    // weights: 1800 float4
#pragma unroll
    for (int it = 0; it < 8; ++it) {
        int idx = tid + it * 256;
        if (idx < 1800)
            cp16(w_dst + idx * 16, wsrc + idx, 16);
    }
}

// conv1 inner compute: CNT output channels, 4 row-pair accumulators
template<int CNT>
__device__ __forceinline__ void c1_compute(const float* __restrict__ s_raw,
                                           const float2* __restrict__ s_w,
                                           int tx, int base, ull acc[4][7])
{
#pragma unroll 1
    for (int c = 0; c < 8; ++c) {
#pragma unroll
        for (int kx = 0; kx < 3; ++kx) {
            float v[10];
#pragma unroll
            for (int r = 0; r < 10; ++r)
                v[r] = s_raw[(c * 10 + r) * 40 + tx + kx + 3];
            ull pe[5], po[4];
#pragma unroll
            for (int j = 0; j < 5; ++j) pe[j] = pk2(v[2 * j], v[2 * j + 1]);
#pragma unroll
            for (int j = 0; j < 4; ++j) po[j] = pk2(v[2 * j + 1], v[2 * j + 2]);
            const ull* w0p = (const ull*)(s_w + (c * 9 + 0 * 3 + kx) * C1 + base);
            const ull* w1p = (const ull*)(s_w + (c * 9 + 1 * 3 + kx) * C1 + base);
            const ull* w2p = (const ull*)(s_w + (c * 9 + 2 * 3 + kx) * C1 + base);
#pragma unroll
            for (int q = 0; q < CNT; ++q) {
                ull wa = w0p[q];
                fma2(acc[0][q], pe[0], wa); fma2(acc[1][q], pe[1], wa);
                fma2(acc[2][q], pe[2], wa); fma2(acc[3][q], pe[3], wa);
                ull wb = w1p[q];
                fma2(acc[0][q], po[0], wb); fma2(acc[1][q], po[1], wb);
                fma2(acc[2][q], po[2], wb); fma2(acc[3][q], po[3], wb);
                ull wc = w2p[q];
                fma2(acc[0][q], pe[1], wc); fma2(acc[1][q], pe[2], wc);
                fma2(acc[2][q], pe[3], wc); fma2(acc[3][q], pe[4], wc);
            }
        }
    }
}

// ---------------------------------------------------------------------------
// conv1: ctrl [8,128,128,128] -> relu -> BN -> g_h [8,50,128,128]
// block: 32x8 pixel tile, 256 thr = 32 px-cols x 8 warps. Warps 0-1 own 7
// output channels, warps 2-7 own 6 (50 exact). cp.async double-buffered
// staging overlaps gmem latency with FFMA2 compute.   (exact R7 code)
// ---------------------------------------------------------------------------
__global__ __launch_bounds__(256, 2)
void conv1_kernel(const float* __restrict__ ctrl,
                  const float* __restrict__ b1, const float* __restrict__ gamma,
                  const float* __restrict__ beta, const float* __restrict__ mean,
                  const float* __restrict__ var)
{
    extern __shared__ float sdyn[];
    float*  s_raw = sdyn;                                // [2][3200]
    float2* s_w   = (float2*)(sdyn + 2 * C1_RAW_FLOATS); // [2][3600]
    const uint32_t raw_u = smem_u32(s_raw);
    const uint32_t w_u   = smem_u32(s_w);

    const int tid = threadIdx.x;
    const int tx = tid & 31;
    const int cg = tid >> 5;             // warp id 0..7
    const int x0 = blockIdx.x * 32;
    const int y0 = blockIdx.y * 8;
    const int b  = blockIdx.z;

    const int cnt  = (cg < 2) ? 7 : 6;
    const int base = (cg < 2) ? cg * 7 : 14 + (cg - 2) * 6;

    ull acc[4][7];
#pragma unroll
    for (int j = 0; j < 4; ++j)
#pragma unroll
        for (int q = 0; q < 7; ++q) acc[j][q] = 0ULL;

    const float* ctrl_b = ctrl + (size_t)b * CIN * NHW * NHW;

    // prologue: stage chunk 0 into buffer 0
    c1_stage(ctrl_b, (const float4*)(g_wdup), y0, x0, tid, raw_u, w_u);
    cp_commit();

    int buf = 0;
#pragma unroll 1
    for (int k = 0; k < 16; ++k) {
        if (k < 15) {
            int nb = buf ^ 1;
            c1_stage(ctrl_b + (k + 1) * 8 * (NHW * NHW),
                     (const float4*)(g_wdup + (k + 1) * 8 * (9 * C1)),
                     y0, x0, tid,
                     raw_u + nb * (C1_RAW_FLOATS * 4),
                     w_u + nb * (C1_W_F2 * 8));
        }
        cp_commit();
        cp_wait1();
        __syncthreads();

        const float*  rb = s_raw + buf * C1_RAW_FLOATS;
        const float2* wb = s_w + buf * C1_W_F2;
        if (cg < 2) c1_compute<7>(rb, wb, tx, base, acc);
        else        c1_compute<6>(rb, wb, tx, base, acc);
        __syncthreads();
        buf ^= 1;
    }

    // epilogue: bias -> relu -> BN -> store
#pragma unroll
    for (int q = 0; q < 7; ++q) {
        if (q < cnt) {
            int oc = base + q;
            float bb = b1[oc];
            float sc = gamma[oc] * rsqrtf(var[oc] + 1e-5f);
            float bt = beta[oc] - mean[oc] * sc;
            float* hp = g_h + (((size_t)b * C1 + oc) * NHW + y0) * NHW + x0 + tx;
#pragma unroll
            for (int j = 0; j < 4; ++j) {
                float lo, hi;
                upk2(acc[j][q], lo, hi);
                hp[(2 * j) * NHW]     = fmaxf(lo + bb, 0.f) * sc + bt;
                hp[(2 * j + 1) * NHW] = fmaxf(hi + bb, 0.f) * sc + bt;
            }
        }
    }
}

// conv2 smem layout (dynamic):
//   s_in:  [2][5][18][40] float = 28800 B  (input rows, 4-col halo pad)
//   s_w2:  [50][9][9] float2    = 32400 B  (ALL weights as channel pairs)
#define C2_IN_FLOATS (5 * 18 * 40)      // per buffer: 3600
#define C2_W_F2      (C1 * 9 * 9)       // 4050
#define C2_SMEM_BYTES (2 * C2_IN_FLOATS * 4 + C2_W_F2 * 8)   // 61200

// stage one 5-channel input chunk via cp.async (18 rows incl. halo)
__device__ __forceinline__ void c2_stage(const float* __restrict__ h_chunk,
                                         int y0, int x0, int tid,
                                         uint32_t in_dst)
{
    // 5c x 18r x 10 groups of 16B = 900 ops
#pragma unroll
    for (int it = 0; it < 4; ++it) {
        int idx = tid + it * 256;
        if (idx < 900) {
            int c = idx / 180, rem = idx - c * 180;
            int r = rem / 10, g = rem - r * 10;
            int y = y0 + r - 1;
            int gx = x0 - 4 + g * 4;
            bool ok = ((unsigned)y < (unsigned)NHW) && ((unsigned)gx <= 124u);
            int soff = ok ? (c * (NHW * NHW) + y * NHW + gx) : 0;
            cp16(in_dst + ((c * 18 + r) * 40 + g * 4) * 4,
                 h_chunk + soff, ok ? 16 : 0);
        }
    }
}

// ---------------------------------------------------------------------------
// conv2: g_h [8,50,128,128] -> g_cond [8,18,128,128]
// block: 32x16 tile -> grid 4x8x8 = 256 CTAs (2 per SM, occupancy-driven).
// 256 thr = 32 cols x 8 row-groups; thread: 2 rows x 18 ch (9 f32x2 pairs).
// cp.async double-buffered input; all weights staged to smem once.
// ---------------------------------------------------------------------------
__global__ __launch_bounds__(256, 2)
void conv2_kernel(const float* __restrict__ w2, const float* __restrict__ b2)
{
    extern __shared__ float sdyn[];
    float*  s_in = sdyn;                                // [2][3600]
    float2* s_w2 = (float2*)(sdyn + 2 * C2_IN_FLOATS);  // [4050]
    const uint32_t in_u = smem_u32(s_in);

    const int tid = threadIdx.x;
    const int tx = tid & 31;
    const int rg = tid >> 5;
    const int x0 = blockIdx.x * 32;
    const int y0 = blockIdx.y * 16;
    const int b  = blockIdx.z;

    ull acc[2][9];
#pragma unroll
    for (int r = 0; r < 2; ++r)
#pragma unroll
        for (int q = 0; q < 9; ++q) acc[r][q] = 0ULL;

    const float* h_b = g_h + (size_t)b * C1 * NHW * NHW;

    // stage ALL weights once (plain LDG->STS): [ch][kk][q2] channel pairs
    for (int idx = tid; idx < C2_W_F2; idx += 256) {
        int ch = idx / 81, rem = idx - ch * 81;
        int kk = rem / 9, q2 = rem - kk * 9;
        s_w2[idx] = make_float2(w2[(2 * q2)     * (C1 * 9) + ch * 9 + kk],
                                w2[(2 * q2 + 1) * (C1 * 9) + ch * 9 + kk]);
    }

    // prologue: stage input chunk 0 into buffer 0
    c2_stage(h_b, y0, x0, tid, in_u);
    cp_commit();

    int buf = 0;
#pragma unroll 1
    for (int k = 0; k < 10; ++k) {
        if (k < 9)
            c2_stage(h_b + (k + 1) * 5 * (NHW * NHW), y0, x0, tid,
                     in_u + (buf ^ 1) * (C2_IN_FLOATS * 4));
        cp_commit();
        cp_wait1();
        __syncthreads();

        const float* ib = s_in + buf * C2_IN_FLOATS;
        const int rbase = rg * 2;
#pragma unroll 1
        for (int c = 0; c < 5; ++c) {
            const float2* wch = s_w2 + (k * 5 + c) * 81;
#pragma unroll
            for (int kx = 0; kx < 3; ++kx) {
                ull pr[4];
#pragma unroll
                for (int r = 0; r < 4; ++r) {
                    float v = ib[(c * 18 + rbase + r) * 40 + tx + kx + 3];
                    pr[r] = pk2(v, v);
                }
#pragma unroll
                for (int ky = 0; ky < 3; ++ky) {
                    const ull* wrow = (const ull*)(wch + (ky * 3 + kx) * 9);
#pragma unroll
                    for (int q2 = 0; q2 < 9; ++q2) {
                        ull wv = wrow[q2];
                        fma2(acc[0][q2], pr[0 + ky], wv);
                        fma2(acc[1][q2], pr[1 + ky], wv);
                    }
                }
            }
        }
        __syncthreads();
        buf ^= 1;
    }

#pragma unroll
    for (int q2 = 0; q2 < 9; ++q2) {
        float bl = b2[2 * q2], bh = b2[2 * q2 + 1];
        float* p0 = g_cond + (((size_t)b * C2 + 2 * q2) * NHW + y0 + rg * 2) * NHW + x0 + tx;
        float* p1 = p0 + (size_t)NHW * NHW;
#pragma unroll
        for (int r = 0; r < 2; ++r) {
            float lo, hi;
            upk2(acc[r][q2], lo, hi);
            p0[r * NHW] = lo + bl;
            p1[r * NHW] = hi + bh;
        }
    }
}

// ---------------------------------------------------------------------------
// dynamic 9-tap cell-strided filter (exact R7 version, 4 px per thread).
// out[b,ch,y,x] = sum_k img[b,ch, y+(j-1)*4, x+(i-1)*4] * cond[b, g*9+k, y/4, x/4]
// k = i*3 + j, g = ch/3. One thread per float4 (4-aligned -> all taps aligned).
// ---------------------------------------------------------------------------
__global__ __launch_bounds__(256)
void dynfilt_kernel(const float* __restrict__ img, float* __restrict__ out)
{
    int tid = blockIdx.x * 256 + threadIdx.x;   // 8*6*512*128 threads
    int x4 = tid & 127;
    int y  = (tid >> 7) & 511;
    int bc = tid >> 16;            // b*6 + ch
    int ch = bc % 6;
    int b  = bc / 6;
    int g  = ch / 3;

    const float* wp = g_cond + (((size_t)b * C2 + g * 9) * NHW + (y >> 2)) * NHW + x4;
    float w[9];
#pragma unroll
    for (int k = 0; k < 9; ++k) w[k] = wp[(size_t)k * (NHW * NHW)];

    const float* ip = img + ((size_t)b * 6 + ch) * (HH * WW);
    int x = x4 * 4;
    float4 acc = make_float4(0.f, 0.f, 0.f, 0.f);
#pragma unroll
    for (int i = 0; i < 3; ++i) {
        int xx = x + (i - 1) * 4;
        bool xok = (unsigned)xx < (unsigned)WW;
#pragma unroll
        for (int j = 0; j < 3; ++j) {
            int yy = y + (j - 1) * 4;
            float4 v = make_float4(0.f, 0.f, 0.f, 0.f);
            if (xok && (unsigned)yy < (unsigned)HH)
                v = *(const float4*)(ip + (size_t)yy * WW + xx);
            float wk = w[i * 3 + j];
            acc.x = fmaf(v.x, wk, acc.x);
            acc.y = fmaf(v.y, wk, acc.y);
            acc.z = fmaf(v.z, wk, acc.z);
            acc.w = fmaf(v.w, wk, acc.w);
        }
    }
    *(float4*)(out + (((size_t)b * 6 + ch) * HH + y) * WW + x) = acc;
}

// ---------------------------------------------------------------------------
extern "C" void kernel_launch(void* const* d_in, const int* in_sizes, int n_in,
                              void* d_out, int out_size)
{
    const float* image = (const float*)d_in[0];
    const float* ctrl  = (const float*)d_in[1];
    const float* w1    = (const float*)d_in[2];
    const float* b1    = (const float*)d_in[3];
    const float* gamma = (const float*)d_in[4];
    const float* beta  = (const float*)d_in[5];
    const float* mean  = (const float*)d_in[6];
    const float* var   = (const float*)d_in[7];
    const float* w2    = (const float*)d_in[8];
    const float* b2    = (const float*)d_in[9];
    float* out = (float*)d_out;

    cudaFuncSetAttribute(conv1_kernel,
                         cudaFuncAttributeMaxDynamicSharedMemorySize, C1_SMEM_BYTES);
    cudaFuncSetAttribute(conv2_kernel,
                         cudaFuncAttributeMaxDynamicSharedMemorySize, C2_SMEM_BYTES);

    setup_w1_kernel<<<(CIN * 9 * C1 + 255) / 256, 256>>>(w1);
    conv1_kernel<<<dim3(4, 16, BATCH), 256, C1_SMEM_BYTES>>>(ctrl, b1, gamma, beta, mean, var);
    conv2_kernel<<<dim3(4, 8, BATCH), 256, C2_SMEM_BYTES>>>(w2, b2);
    dynfilt_kernel<<<(BATCH * 6 * HH * (WW / 4)) / 256, 256>>>(image, out);
}

// round 13
// speedup vs baseline: 1.0196x; 1.0196x over previous
#include <cuda_runtime.h>
#include <cstdint>

#define CIN  128
#define NHW  128
#define C1   50
#define C2   18
#define BATCH 8
#define HH   512
#define WW   512

typedef unsigned long long ull;

// scratch (allocation-free rule: device globals)
__device__ float g_h[BATCH * C1 * NHW * NHW];       // conv1 output (26.2 MB)
__device__ float g_cond[BATCH * C2 * NHW * NHW];    // conv2 output (9.4 MB)
__device__ __align__(16) float2 g_wdup[CIN * 9 * C1];  // conv1 weights, duplicated (w,w), chunk-contiguous

__device__ __forceinline__ ull pk2(float lo, float hi) {
    ull r;
    asm("mov.b64 %0, {%1, %2};" : "=l"(r) : "f"(lo), "f"(hi));
    return r;
}
__device__ __forceinline__ void upk2(ull v, float& lo, float& hi) {
    asm("mov.b64 {%0, %1}, %2;" : "=f"(lo), "=f"(hi) : "l"(v));
}
__device__ __forceinline__ void fma2(ull& d, ull a, ull b) {
    asm("fma.rn.f32x2 %0, %1, %2, %3;" : "=l"(d) : "l"(a), "l"(b), "l"(d));
}
__device__ __forceinline__ uint32_t smem_u32(const void* p) {
    uint32_t a;
    asm("{ .reg .u64 t; cvta.to.shared.u64 t, %1; cvt.u32.u64 %0, t; }"
        : "=r"(a) : "l"(p));
    return a;
}
__device__ __forceinline__ void cp16(uint32_t dst, const void* src, int sz) {
    asm volatile("cp.async.cg.shared.global [%0], [%1], 16, %2;"
                 :: "r"(dst), "l"(src), "r"(sz) : "memory");
}
__device__ __forceinline__ void cp_commit() {
    asm volatile("cp.async.commit_group;" ::: "memory");
}
__device__ __forceinline__ void cp_wait1() {
    asm volatile("cp.async.wait_group 1;" ::: "memory");
}

// ---------------------------------------------------------------------------
// setup: duplicate conv1 weights into (w,w) float2, layout [cin][kk][oc]
// ---------------------------------------------------------------------------
__global__ void setup_w1_kernel(const float* __restrict__ w1)
{
    int i = blockIdx.x * 256 + threadIdx.x;       // 128*9*50 = 57600
    if (i < CIN * 9 * C1) {
        int cin = i / (9 * C1);
        int rem = i - cin * (9 * C1);
        int kk  = rem / C1;
        int oc  = rem - kk * C1;
        float w = w1[oc * (CIN * 9) + cin * 9 + kk];
        g_wdup[i] = make_float2(w, w);
    }
}

// conv1 smem layout (dynamic):
//   s_raw: [2][8][10][40] float  = 25600 B
//   s_w:   [2][8][9][50] float2  = 57600 B
#define C1_RAW_FLOATS (8 * 10 * 40)
#define C1_W_F2       (8 * 9 * 50)
#define C1_SMEM_BYTES (2 * C1_RAW_FLOATS * 4 + 2 * C1_W_F2 * 8)   // 83200

__device__ __forceinline__ void c1_stage(const float* __restrict__ ctrl_chunk,
                                         const float4* __restrict__ wsrc,
                                         int y0, int x0, int tid,
                                         uint32_t raw_dst, uint32_t w_dst)
{
#pragma unroll
    for (int it = 0; it < 4; ++it) {
        int idx = tid + it * 256;
        if (idx < 800) {
            int c = idx / 100, rem = idx - c * 100;
            int r = rem / 10, g = rem - r * 10;
            int y = y0 + r - 1;
            int gx = x0 - 4 + g * 4;
            bool ok = ((unsigned)y < (unsigned)NHW) && ((unsigned)gx <= 124u);
            int soff = ok ? (c * (NHW * NHW) + y * NHW + gx) : 0;
            cp16(raw_dst + ((c * 10 + r) * 40 + g * 4) * 4,
                 ctrl_chunk + soff, ok ? 16 : 0);
        }
    }
#pragma unroll
    for (int it = 0; it < 8; ++it) {
        int idx = tid + it * 256;
        if (idx < 1800)
            cp16(w_dst + idx * 16, wsrc + idx, 16);
    }
}

template<int CNT>
__device__ __forceinline__ void c1_compute(const float* __restrict__ s_raw,
                                           const float2* __restrict__ s_w,
                                           int tx, int base, ull acc[4][7])
{
#pragma unroll 1
    for (int c = 0; c < 8; ++c) {
#pragma unroll
        for (int kx = 0; kx < 3; ++kx) {
            float v[10];
#pragma unroll
            for (int r = 0; r < 10; ++r)
                v[r] = s_raw[(c * 10 + r) * 40 + tx + kx + 3];
            ull pe[5], po[4];
#pragma unroll
            for (int j = 0; j < 5; ++j) pe[j] = pk2(v[2 * j], v[2 * j + 1]);
#pragma unroll
            for (int j = 0; j < 4; ++j) po[j] = pk2(v[2 * j + 1], v[2 * j + 2]);
            const ull* w0p = (const ull*)(s_w + (c * 9 + 0 * 3 + kx) * C1 + base);
            const ull* w1p = (const ull*)(s_w + (c * 9 + 1 * 3 + kx) * C1 + base);
            const ull* w2p = (const ull*)(s_w + (c * 9 + 2 * 3 + kx) * C1 + base);
#pragma unroll
            for (int q = 0; q < CNT; ++q) {
                ull wa = w0p[q];
                fma2(acc[0][q], pe[0], wa); fma2(acc[1][q], pe[1], wa);
                fma2(acc[2][q], pe[2], wa); fma2(acc[3][q], pe[3], wa);
                ull wb = w1p[q];
                fma2(acc[0][q], po[0], wb); fma2(acc[1][q], po[1], wb);
                fma2(acc[2][q], po[2], wb); fma2(acc[3][q], po[3], wb);
                ull wc = w2p[q];
                fma2(acc[0][q], pe[1], wc); fma2(acc[1][q], pe[2], wc);
                fma2(acc[2][q], pe[3], wc); fma2(acc[3][q], pe[4], wc);
            }
        }
    }
}

// ---------------------------------------------------------------------------
// conv1 (exact R7 code): 32x8 tile, 256 thr, cp.async double-buffered.
// ---------------------------------------------------------------------------
__global__ __launch_bounds__(256, 2)
void conv1_kernel(const float* __restrict__ ctrl,
                  const float* __restrict__ b1, const float* __restrict__ gamma,
                  const float* __restrict__ beta, const float* __restrict__ mean,
                  const float* __restrict__ var)
{
    extern __shared__ float sdyn[];
    float*  s_raw = sdyn;
    float2* s_w   = (float2*)(sdyn + 2 * C1_RAW_FLOATS);
    const uint32_t raw_u = smem_u32(s_raw);
    const uint32_t w_u   = smem_u32(s_w);

    const int tid = threadIdx.x;
    const int tx = tid & 31;
    const int cg = tid >> 5;
    const int x0 = blockIdx.x * 32;
    const int y0 = blockIdx.y * 8;
    const int b  = blockIdx.z;

    const int cnt  = (cg < 2) ? 7 : 6;
    const int base = (cg < 2) ? cg * 7 : 14 + (cg - 2) * 6;

    ull acc[4][7];
#pragma unroll
    for (int j = 0; j < 4; ++j)
#pragma unroll
        for (int q = 0; q < 7; ++q) acc[j][q] = 0ULL;

    const float* ctrl_b = ctrl + (size_t)b * CIN * NHW * NHW;

    c1_stage(ctrl_b, (const float4*)(g_wdup), y0, x0, tid, raw_u, w_u);
    cp_commit();

    int buf = 0;
#pragma unroll 1
    for (int k = 0; k < 16; ++k) {
        if (k < 15) {
            int nb = buf ^ 1;
            c1_stage(ctrl_b + (k + 1) * 8 * (NHW * NHW),
                     (const float4*)(g_wdup + (k + 1) * 8 * (9 * C1)),
                     y0, x0, tid,
                     raw_u + nb * (C1_RAW_FLOATS * 4),
                     w_u + nb * (C1_W_F2 * 8));
        }
        cp_commit();
        cp_wait1();
        __syncthreads();

        const float*  rb = s_raw + buf * C1_RAW_FLOATS;
        const float2* wb = s_w + buf * C1_W_F2;
        if (cg < 2) c1_compute<7>(rb, wb, tx, base, acc);
        else        c1_compute<6>(rb, wb, tx, base, acc);
        __syncthreads();
        buf ^= 1;
    }

#pragma unroll
    for (int q = 0; q < 7; ++q) {
        if (q < cnt) {
            int oc = base + q;
            float bb = b1[oc];
            float sc = gamma[oc] * rsqrtf(var[oc] + 1e-5f);
            float bt = beta[oc] - mean[oc] * sc;
            float* hp = g_h + (((size_t)b * C1 + oc) * NHW + y0) * NHW + x0 + tx;
#pragma unroll
            for (int j = 0; j < 4; ++j) {
                float lo, hi;
                upk2(acc[j][q], lo, hi);
                hp[(2 * j) * NHW]     = fmaxf(lo + bb, 0.f) * sc + bt;
                hp[(2 * j + 1) * NHW] = fmaxf(hi + bb, 0.f) * sc + bt;
            }
        }
    }
}

// ---------------------------------------------------------------------------
// conv2 (exact R7 code): 32x32 tile, static smem, 256 thr.
// ---------------------------------------------------------------------------
__global__ __launch_bounds__(256)
void conv2_kernel(const float* __restrict__ w2, const float* __restrict__ b2)
{
    __shared__ float  s_in[5][34][34];
    __shared__ float2 s_w[5][9][9];

    const int tx = threadIdx.x & 31;
    const int rg = threadIdx.x >> 5;
    const int x0 = blockIdx.x * 32;
    const int y0 = blockIdx.y * 32;
    const int b  = blockIdx.z;

    ull acc[4][9];
#pragma unroll
    for (int r = 0; r < 4; ++r)
#pragma unroll
        for (int q = 0; q < 9; ++q) acc[r][q] = 0ULL;

    for (int ch = 0; ch < C1; ch += 5) {
        __syncthreads();
        for (int idx = threadIdx.x; idx < 5 * 34 * 34; idx += 256) {
            int c = idx / 1156, rem = idx - c * 1156;
            int r = rem / 34, cl = rem - r * 34;
            int y = y0 + r - 1, x = x0 + cl - 1;
            float v = 0.f;
            if ((unsigned)y < (unsigned)NHW && (unsigned)x < (unsigned)NHW)
                v = g_h[(((size_t)b * C1 + ch + c) * NHW + y) * NHW + x];
            s_in[c][r][cl] = v;
        }
        for (int idx = threadIdx.x; idx < 5 * 9 * 9; idx += 256) {
            int c = idx / 81, rem = idx - c * 81;
            int kk = rem / 9, q2 = rem - kk * 9;
            s_w[c][kk][q2] = make_float2(
                w2[(2 * q2)     * (C1 * 9) + (ch + c) * 9 + kk],
                w2[(2 * q2 + 1) * (C1 * 9) + (ch + c) * 9 + kk]);
        }
        __syncthreads();

        const int rbase = rg * 4;
#pragma unroll 1
        for (int c = 0; c < 5; ++c) {
#pragma unroll
            for (int kx = 0; kx < 3; ++kx) {
                ull pr[6];
#pragma unroll
                for (int r = 0; r < 6; ++r) {
                    float v = s_in[c][rbase + r][tx + kx];
                    pr[r] = pk2(v, v);
                }
#pragma unroll
                for (int ky = 0; ky < 3; ++ky) {
                    const ull* wrow = (const ull*)&s_w[c][ky * 3 + kx][0];
#pragma unroll
                    for (int q2 = 0; q2 < 9; ++q2) {
                        ull wv = wrow[q2];
                        fma2(acc[0][q2], pr[0 + ky], wv);
                        fma2(acc[1][q2], pr[1 + ky], wv);
                        fma2(acc[2][q2], pr[2 + ky], wv);
                        fma2(acc[3][q2], pr[3 + ky], wv);
                    }
                }
            }
        }
    }

#pragma unroll
    for (int q2 = 0; q2 < 9; ++q2) {
        float bl = b2[2 * q2], bh = b2[2 * q2 + 1];
        float* p0 = g_cond + (((size_t)b * C2 + 2 * q2) * NHW + y0 + rg * 4) * NHW + x0 + tx;
        float* p1 = p0 + (size_t)NHW * NHW;
#pragma unroll
        for (int r = 0; r < 4; ++r) {
            float lo, hi;
            upk2(acc[r][q2], lo, hi);
            p0[r * NHW] = lo + bl;
            p1[r * NHW] = hi + bh;
        }
    }
}

// ---------------------------------------------------------------------------
// dynamic 9-tap cell-strided filter: 2 output rows (same cell => same 9
// weights) x 4 px per thread, with a branch-free interior fast path.
// out[b,ch,y,x] = sum_k img[b,ch, y+(j-1)*4, x+(i-1)*4] * cond[b, g*9+k, y/4, x/4]
// ---------------------------------------------------------------------------
__global__ __launch_bounds__(256)
void dynfilt_kernel(const float* __restrict__ img, float* __restrict__ out)
{
    int tid = blockIdx.x * 256 + threadIdx.x;   // 8*6*256*128 threads
    int x4 = tid & 127;
    int yp = (tid >> 7) & 255;     // row-pair index; y = 2*yp, rows y and y+1
    int bc = tid >> 15;            // b*6 + ch
    int ch = bc % 6;
    int b  = bc / 6;
    int g  = ch / 3;
    int y  = yp * 2;
    int x  = x4 * 4;

    // rows y and y+1 share the same cell row (y>>2): one weight set
    const float* wp = g_cond + (((size_t)b * C2 + g * 9) * NHW + (y >> 2)) * NHW + x4;
    float w[9];
#pragma unroll
    for (int k = 0; k < 9; ++k) w[k] = wp[(size_t)k * (NHW * NHW)];

    const float* ip = img + ((size_t)b * 6 + ch) * (HH * WW);
    float4 a0 = make_float4(0.f, 0.f, 0.f, 0.f);
    float4 a1 = make_float4(0.f, 0.f, 0.f, 0.f);

    bool interior = (x >= 4) && (x <= WW - 8) && (y >= 4) && (y + 1 + 4 < HH);
    if (interior) {
#pragma unroll
        for (int j = 0; j < 3; ++j) {
            const float* r0 = ip + (size_t)(y + (j - 1) * 4) * WW + x;
            const float* r1 = r0 + WW;
#pragma unroll
            for (int i = 0; i < 3; ++i) {
                float4 v0 = *(const float4*)(r0 + (i - 1) * 4);
                float4 v1 = *(const float4*)(r1 + (i - 1) * 4);
                float wk = w[i * 3 + j];
                a0.x = fmaf(v0.x, wk, a0.x); a0.y = fmaf(v0.y, wk, a0.y);
                a0.z = fmaf(v0.z, wk, a0.z); a0.w = fmaf(v0.w, wk, a0.w);
                a1.x = fmaf(v1.x, wk, a1.x); a1.y = fmaf(v1.y, wk, a1.y);
                a1.z = fmaf(v1.z, wk, a1.z); a1.w = fmaf(v1.w, wk, a1.w);
            }
        }
    } else {
#pragma unroll
        for (int i = 0; i < 3; ++i) {
            int xx = x + (i - 1) * 4;
            bool xok = (unsigned)xx < (unsigned)WW;
#pragma unroll
            for (int j = 0; j < 3; ++j) {
                int yy = y + (j - 1) * 4;
                float wk = w[i * 3 + j];
                float4 v0 = make_float4(0.f, 0.f, 0.f, 0.f);
                float4 v1 = v0;
                if (xok && (unsigned)yy < (unsigned)HH)
                    v0 = *(const float4*)(ip + (size_t)yy * WW + xx);
                if (xok && (unsigned)(yy + 1) < (unsigned)HH)
                    v1 = *(const float4*)(ip + (size_t)(yy + 1) * WW + xx);
                a0.x = fmaf(v0.x, wk, a0.x); a0.y = fmaf(v0.y, wk, a0.y);
                a0.z = fmaf(v0.z, wk, a0.z); a0.w = fmaf(v0.w, wk, a0.w);
                a1.x = fmaf(v1.x, wk, a1.x); a1.y = fmaf(v1.y, wk, a1.y);
                a1.z = fmaf(v1.z, wk, a1.z); a1.w = fmaf(v1.w, wk, a1.w);
            }
        }
    }
    float* op = out + (((size_t)b * 6 + ch) * HH + y) * WW + x;
    *(float4*)op        = a0;
    *(float4*)(op + WW) = a1;
}

// ---------------------------------------------------------------------------
extern "C" void kernel_launch(void* const* d_in, const int* in_sizes, int n_in,
                              void* d_out, int out_size)
{
    const float* image = (const float*)d_in[0];
    const float* ctrl  = (const float*)d_in[1];
    const float* w1    = (const float*)d_in[2];
    const float* b1    = (const float*)d_in[3];
    const float* gamma = (const float*)d_in[4];
    const float* beta  = (const float*)d_in[5];
    const float* mean  = (const float*)d_in[6];
    const float* var   = (const float*)d_in[7];
    const float* w2    = (const float*)d_in[8];
    const float* b2    = (const float*)d_in[9];
    float* out = (float*)d_out;

    cudaFuncSetAttribute(conv1_kernel,
                         cudaFuncAttributeMaxDynamicSharedMemorySize, C1_SMEM_BYTES);

    setup_w1_kernel<<<(CIN * 9 * C1 + 255) / 256, 256>>>(w1);
    conv1_kernel<<<dim3(4, 16, BATCH), 256, C1_SMEM_BYTES>>>(ctrl, b1, gamma, beta, mean, var);
    conv2_kernel<<<dim3(4, 4, BATCH), 256>>>(w2, b2);
    dynfilt_kernel<<<(BATCH * 6 * (HH / 2) * (WW / 4)) / 256, 256>>>(image, out);
}

// round 14
// speedup vs baseline: 1.0275x; 1.0077x over previous
#include <cuda_runtime.h>
#include <cstdint>

#define CIN  128
#define NHW  128
#define C1   50
#define C2   18
#define BATCH 8
#define HH   512
#define WW   512

typedef unsigned long long ull;

// scratch (allocation-free rule: device globals)
__device__ float g_h[BATCH * C1 * NHW * NHW];          // conv1 output (26.2 MB)
__device__ float g_part[2 * BATCH * C2 * NHW * NHW];   // conv2 split-K partials (18.9 MB)
__device__ __align__(16) float2 g_wdup[CIN * 9 * C1];  // conv1 weights, duplicated (w,w)

__device__ __forceinline__ ull pk2(float lo, float hi) {
    ull r;
    asm("mov.b64 %0, {%1, %2};" : "=l"(r) : "f"(lo), "f"(hi));
    return r;
}
__device__ __forceinline__ void upk2(ull v, float& lo, float& hi) {
    asm("mov.b64 {%0, %1}, %2;" : "=f"(lo), "=f"(hi) : "l"(v));
}
__device__ __forceinline__ void fma2(ull& d, ull a, ull b) {
    asm("fma.rn.f32x2 %0, %1, %2, %3;" : "=l"(d) : "l"(a), "l"(b), "l"(d));
}
__device__ __forceinline__ uint32_t smem_u32(const void* p) {
    uint32_t a;
    asm("{ .reg .u64 t; cvta.to.shared.u64 t, %1; cvt.u32.u64 %0, t; }"
        : "=r"(a) : "l"(p));
    return a;
}
__device__ __forceinline__ void cp16(uint32_t dst, const void* src, int sz) {
    asm volatile("cp.async.cg.shared.global [%0], [%1], 16, %2;"
                 :: "r"(dst), "l"(src), "r"(sz) : "memory");
}
__device__ __forceinline__ void cp_commit() {
    asm volatile("cp.async.commit_group;" ::: "memory");
}
__device__ __forceinline__ void cp_wait1() {
    asm volatile("cp.async.wait_group 1;" ::: "memory");
}

// ---------------------------------------------------------------------------
// setup: duplicate conv1 weights into (w,w) float2, layout [cin][kk][oc]
// ---------------------------------------------------------------------------
__global__ void setup_w1_kernel(const float* __restrict__ w1)
{
    int i = blockIdx.x * 256 + threadIdx.x;       // 128*9*50 = 57600
    if (i < CIN * 9 * C1) {
        int cin = i / (9 * C1);
        int rem = i - cin * (9 * C1);
        int kk  = rem / C1;
        int oc  = rem - kk * C1;
        float w = w1[oc * (CIN * 9) + cin * 9 + kk];
        g_wdup[i] = make_float2(w, w);
    }
}

// conv1 smem layout (dynamic):
//   s_raw: [2][8][10][40] float  = 25600 B
//   s_w:   [2][8][9][50] float2  = 57600 B
#define C1_RAW_FLOATS (8 * 10 * 40)
#define C1_W_F2       (8 * 9 * 50)
#define C1_SMEM_BYTES (2 * C1_RAW_FLOATS * 4 + 2 * C1_W_F2 * 8)   // 83200

__device__ __forceinline__ void c1_stage(const float* __restrict__ ctrl_chunk,
                                         const float4* __restrict__ wsrc,
                                         int y0, int x0, int tid,
                                         uint32_t raw_dst, uint32_t w_dst)
{
#pragma unroll
    for (int it = 0; it < 4; ++it) {
        int idx = tid + it * 256;
        if (idx < 800) {
            int c = idx / 100, rem = idx - c * 100;
            int r = rem / 10, g = rem - r * 10;
            int y = y0 + r - 1;
            int gx = x0 - 4 + g * 4;
            bool ok = ((unsigned)y < (unsigned)NHW) && ((unsigned)gx <= 124u);
            int soff = ok ? (c * (NHW * NHW) + y * NHW + gx) : 0;
            cp16(raw_dst + ((c * 10 + r) * 40 + g * 4) * 4,
                 ctrl_chunk + soff, ok ? 16 : 0);
        }
    }
#pragma unroll
    for (int it = 0; it < 8; ++it) {
        int idx = tid + it * 256;
        if (idx < 1800)
            cp16(w_dst + idx * 16, wsrc + idx, 16);
    }
}

template<int CNT>
__device__ __forceinline__ void c1_compute(const float* __restrict__ s_raw,
                                           const float2* __restrict__ s_w,
                                           int tx, int base, ull acc[4][7])
{
#pragma unroll 1
    for (int c = 0; c < 8; ++c) {
#pragma unroll
        for (int kx = 0; kx < 3; ++kx) {
            float v[10];
#pragma unroll
            for (int r = 0; r < 10; ++r)
                v[r] = s_raw[(c * 10 + r) * 40 + tx + kx + 3];
            ull pe[5], po[4];
#pragma unroll
            for (int j = 0; j < 5; ++j) pe[j] = pk2(v[2 * j], v[2 * j + 1]);
#pragma unroll
            for (int j = 0; j < 4; ++j) po[j] = pk2(v[2 * j + 1], v[2 * j + 2]);
            const ull* w0p = (const ull*)(s_w + (c * 9 + 0 * 3 + kx) * C1 + base);
            const ull* w1p = (const ull*)(s_w + (c * 9 + 1 * 3 + kx) * C1 + base);
            const ull* w2p = (const ull*)(s_w + (c * 9 + 2 * 3 + kx) * C1 + base);
#pragma unroll
            for (int q = 0; q < CNT; ++q) {
                ull wa = w0p[q];
                fma2(acc[0][q], pe[0], wa); fma2(acc[1][q], pe[1], wa);
                fma2(acc[2][q], pe[2], wa); fma2(acc[3][q], pe[3], wa);
                ull wb = w1p[q];
                fma2(acc[0][q], po[0], wb); fma2(acc[1][q], po[1], wb);
                fma2(acc[2][q], po[2], wb); fma2(acc[3][q], po[3], wb);
                ull wc = w2p[q];
                fma2(acc[0][q], pe[1], wc); fma2(acc[1][q], pe[2], wc);
                fma2(acc[2][q], pe[3], wc); fma2(acc[3][q], pe[4], wc);
            }
        }
    }
}

// ---------------------------------------------------------------------------
// conv1 (exact R7 code): 32x8 tile, 256 thr, cp.async double-buffered.
// ---------------------------------------------------------------------------
__global__ __launch_bounds__(256, 2)
void conv1_kernel(const float* __restrict__ ctrl,
                  const float* __restrict__ b1, const float* __restrict__ gamma,
                  const float* __restrict__ beta, const float* __restrict__ mean,
                  const float* __restrict__ var)
{
    extern __shared__ float sdyn[];
    float*  s_raw = sdyn;
    float2* s_w   = (float2*)(sdyn + 2 * C1_RAW_FLOATS);
    const uint32_t raw_u = smem_u32(s_raw);
    const uint32_t w_u   = smem_u32(s_w);

    const int tid = threadIdx.x;
    const int tx = tid & 31;
    const int cg = tid >> 5;
    const int x0 = blockIdx.x * 32;
    const int y0 = blockIdx.y * 8;
    const int b  = blockIdx.z;

    const int cnt  = (cg < 2) ? 7 : 6;
    const int base = (cg < 2) ? cg * 7 : 14 + (cg - 2) * 6;

    ull acc[4][7];
#pragma unroll
    for (int j = 0; j < 4; ++j)
#pragma unroll
        for (int q = 0; q < 7; ++q) acc[j][q] = 0ULL;

    const float* ctrl_b = ctrl + (size_t)b * CIN * NHW * NHW;

    c1_stage(ctrl_b, (const float4*)(g_wdup), y0, x0, tid, raw_u, w_u);
    cp_commit();

    int buf = 0;
#pragma unroll 1
    for (int k = 0; k < 16; ++k) {
        if (k < 15) {
            int nb = buf ^ 1;
            c1_stage(ctrl_b + (k + 1) * 8 * (NHW * NHW),
                     (const float4*)(g_wdup + (k + 1) * 8 * (9 * C1)),
                     y0, x0, tid,
                     raw_u + nb * (C1_RAW_FLOATS * 4),
                     w_u + nb * (C1_W_F2 * 8));
        }
        cp_commit();
        cp_wait1();
        __syncthreads();

        const float*  rb = s_raw + buf * C1_RAW_FLOATS;
        const float2* wb = s_w + buf * C1_W_F2;
        if (cg < 2) c1_compute<7>(rb, wb, tx, base, acc);
        else        c1_compute<6>(rb, wb, tx, base, acc);
        __syncthreads();
        buf ^= 1;
    }

#pragma unroll
    for (int q = 0; q < 7; ++q) {
        if (q < cnt) {
            int oc = base + q;
            float bb = b1[oc];
            float sc = gamma[oc] * rsqrtf(var[oc] + 1e-5f);
            float bt = beta[oc] - mean[oc] * sc;
            float* hp = g_h + (((size_t)b * C1 + oc) * NHW + y0) * NHW + x0 + tx;
#pragma unroll
            for (int j = 0; j < 4; ++j) {
                float lo, hi;
                upk2(acc[j][q], lo, hi);
                hp[(2 * j) * NHW]     = fmaxf(lo + bb, 0.f) * sc + bt;
                hp[(2 * j + 1) * NHW] = fmaxf(hi + bb, 0.f) * sc + bt;
            }
        }
    }
}

// ---------------------------------------------------------------------------
// conv2 split-K: g_h [8,50,...] -> g_part[half][8,18,...], half = 25 channels.
// grid (4,4,16): z = b + 8*half -> 256 CTAs (2 per SM, chain halved).
// Inner loop identical to the proven R7 conv2 (4 rows x 9 pairs). No bias
// here; dynfilt combines part0 + part1 + b2.
// ---------------------------------------------------------------------------
__global__ __launch_bounds__(256)
void conv2_kernel(const float* __restrict__ w2)
{
    __shared__ float  s_in[5][34][34];
    __shared__ float2 s_w[5][9][9];

    const int tx = threadIdx.x & 31;
    const int rg = threadIdx.x >> 5;
    const int x0 = blockIdx.x * 32;
    const int y0 = blockIdx.y * 32;
    const int b    = blockIdx.z & 7;
    const int half = blockIdx.z >> 3;
    const int chbase = half * 25;

    ull acc[4][9];
#pragma unroll
    for (int r = 0; r < 4; ++r)
#pragma unroll
        for (int q = 0; q < 9; ++q) acc[r][q] = 0ULL;

    for (int kc = 0; kc < 25; kc += 5) {
        const int ch = chbase + kc;
        __syncthreads();
        for (int idx = threadIdx.x; idx < 5 * 34 * 34; idx += 256) {
            int c = idx / 1156, rem = idx - c * 1156;
            int r = rem / 34, cl = rem - r * 34;
            int y = y0 + r - 1, x = x0 + cl - 1;
            float v = 0.f;
            if ((unsigned)y < (unsigned)NHW && (unsigned)x < (unsigned)NHW)
                v = g_h[(((size_t)b * C1 + ch + c) * NHW + y) * NHW + x];
            s_in[c][r][cl] = v;
        }
        for (int idx = threadIdx.x; idx < 5 * 9 * 9; idx += 256) {
            int c = idx / 81, rem = idx - c * 81;
            int kk = rem / 9, q2 = rem - kk * 9;
            s_w[c][kk][q2] = make_float2(
                w2[(2 * q2)     * (C1 * 9) + (ch + c) * 9 + kk],
                w2[(2 * q2 + 1) * (C1 * 9) + (ch + c) * 9 + kk]);
        }
        __syncthreads();

        const int rbase = rg * 4;
#pragma unroll 1
        for (int c = 0; c < 5; ++c) {
#pragma unroll
            for (int kx = 0; kx < 3; ++kx) {
                ull pr[6];
#pragma unroll
                for (int r = 0; r < 6; ++r) {
                    float v = s_in[c][rbase + r][tx + kx];
                    pr[r] = pk2(v, v);
                }
#pragma unroll
                for (int ky = 0; ky < 3; ++ky) {
                    const ull* wrow = (const ull*)&s_w[c][ky * 3 + kx][0];
#pragma unroll
                    for (int q2 = 0; q2 < 9; ++q2) {
                        ull wv = wrow[q2];
                        fma2(acc[0][q2], pr[0 + ky], wv);
                        fma2(acc[1][q2], pr[1 + ky], wv);
                        fma2(acc[2][q2], pr[2 + ky], wv);
                        fma2(acc[3][q2], pr[3 + ky], wv);
                    }
                }
            }
        }
    }

    float* gp = g_part + (size_t)half * (BATCH * C2 * NHW * NHW);
#pragma unroll
    for (int q2 = 0; q2 < 9; ++q2) {
        float* p0 = gp + (((size_t)b * C2 + 2 * q2) * NHW + y0 + rg * 4) * NHW + x0 + tx;
        float* p1 = p0 + (size_t)NHW * NHW;
#pragma unroll
        for (int r = 0; r < 4; ++r) {
            float lo, hi;
            upk2(acc[r][q2], lo, hi);
            p0[r * NHW] = lo;
            p1[r * NHW] = hi;
        }
    }
}

// ---------------------------------------------------------------------------
// dynamic 9-tap cell-strided filter (R7 structure, 4 px per thread).
// Weights = part0 + part1 + b2 (combines the conv2 split-K halves).
// out[b,ch,y,x] = sum_k img[b,ch, y+(j-1)*4, x+(i-1)*4] * w[k], k=i*3+j.
// ---------------------------------------------------------------------------
__global__ __launch_bounds__(256)
void dynfilt_kernel(const float* __restrict__ img, const float* __restrict__ b2,
                    float* __restrict__ out)
{
    int tid = blockIdx.x * 256 + threadIdx.x;   // 8*6*512*128 threads
    int x4 = tid & 127;
    int y  = (tid >> 7) & 511;
    int bc = tid >> 16;            // b*6 + ch
    int ch = bc % 6;
    int b  = bc / 6;
    int g  = ch / 3;

    const float* wp0 = g_part + (((size_t)b * C2 + g * 9) * NHW + (y >> 2)) * NHW + x4;
    const float* wp1 = wp0 + (size_t)BATCH * C2 * NHW * NHW;
    float w[9];
#pragma unroll
    for (int k = 0; k < 9; ++k)
        w[k] = wp0[(size_t)k * (NHW * NHW)] + wp1[(size_t)k * (NHW * NHW)] + b2[g * 9 + k];

    const float* ip = img + ((size_t)b * 6 + ch) * (HH * WW);
    int x = x4 * 4;
    float4 acc = make_float4(0.f, 0.f, 0.f, 0.f);
#pragma unroll
    for (int i = 0; i < 3; ++i) {
        int xx = x + (i - 1) * 4;
        bool xok = (unsigned)xx < (unsigned)WW;
#pragma unroll
        for (int j = 0; j < 3; ++j) {
            int yy = y + (j - 1) * 4;
            float4 v = make_float4(0.f, 0.f, 0.f, 0.f);
            if (xok && (unsigned)yy < (unsigned)HH)
                v = *(const float4*)(ip + (size_t)yy * WW + xx);
            float wk = w[i * 3 + j];
            acc.x = fmaf(v.x, wk, acc.x);
            acc.y = fmaf(v.y, wk, acc.y);
            acc.z = fmaf(v.z, wk, acc.z);
            acc.w = fmaf(v.w, wk, acc.w);
        }
    }
    *(float4*)(out + (((size_t)b * 6 + ch) * HH + y) * WW + x) = acc;
}

// ---------------------------------------------------------------------------
extern "C" void kernel_launch(void* const* d_in, const int* in_sizes, int n_in,
                              void* d_out, int out_size)
{
    const float* image = (const float*)d_in[0];
    const float* ctrl  = (const float*)d_in[1];
    const float* w1    = (const float*)d_in[2];
    const float* b1    = (const float*)d_in[3];
    const float* gamma = (const float*)d_in[4];
    const float* beta  = (const float*)d_in[5];
    const float* mean  = (const float*)d_in[6];
    const float* var   = (const float*)d_in[7];
    const float* w2    = (const float*)d_in[8];
    const float* b2    = (const float*)d_in[9];
    float* out = (float*)d_out;

    cudaFuncSetAttribute(conv1_kernel,
                         cudaFuncAttributeMaxDynamicSharedMemorySize, C1_SMEM_BYTES);

    setup_w1_kernel<<<(CIN * 9 * C1 + 255) / 256, 256>>>(w1);
    conv1_kernel<<<dim3(4, 16, BATCH), 256, C1_SMEM_BYTES>>>(ctrl, b1, gamma, beta, mean, var);
    conv2_kernel<<<dim3(4, 4, 16), 256>>>(w2);
    dynfilt_kernel<<<(BATCH * 6 * HH * (WW / 4)) / 256, 256>>>(image, b2, out);
}

// round 15
// speedup vs baseline: 1.0367x; 1.0090x over previous
#include <cuda_runtime.h>
#include <cstdint>

#define CIN  128
#define NHW  128
#define C1   50
#define C2   18
#define BATCH 8
#define HH   512
#define WW   512

typedef unsigned long long ull;

// scratch (allocation-free rule: device globals)
__device__ float g_h[BATCH * C1 * NHW * NHW];          // conv1 output (26.2 MB)
__device__ float g_part[2 * BATCH * C2 * NHW * NHW];   // conv2 split-K partials (18.9 MB)
__device__ float g_cond[BATCH * C2 * NHW * NHW];       // combined conv2 output (9.4 MB)
__device__ __align__(16) float2 g_wdup[CIN * 9 * C1];  // conv1 weights, duplicated (w,w)

__device__ __forceinline__ ull pk2(float lo, float hi) {
    ull r;
    asm("mov.b64 %0, {%1, %2};" : "=l"(r) : "f"(lo), "f"(hi));
    return r;
}
__device__ __forceinline__ void upk2(ull v, float& lo, float& hi) {
    asm("mov.b64 {%0, %1}, %2;" : "=f"(lo), "=f"(hi) : "l"(v));
}
__device__ __forceinline__ void fma2(ull& d, ull a, ull b) {
    asm("fma.rn.f32x2 %0, %1, %2, %3;" : "=l"(d) : "l"(a), "l"(b), "l"(d));
}
__device__ __forceinline__ uint32_t smem_u32(const void* p) {
    uint32_t a;
    asm("{ .reg .u64 t; cvta.to.shared.u64 t, %1; cvt.u32.u64 %0, t; }"
        : "=r"(a) : "l"(p));
    return a;
}
__device__ __forceinline__ void cp16(uint32_t dst, const void* src, int sz) {
    asm volatile("cp.async.cg.shared.global [%0], [%1], 16, %2;"
                 :: "r"(dst), "l"(src), "r"(sz) : "memory");
}
__device__ __forceinline__ void cp_commit() {
    asm volatile("cp.async.commit_group;" ::: "memory");
}
__device__ __forceinline__ void cp_wait1() {
    asm volatile("cp.async.wait_group 1;" ::: "memory");
}

// ---------------------------------------------------------------------------
// setup: duplicate conv1 weights into (w,w) float2, layout [cin][kk][oc]
// ---------------------------------------------------------------------------
__global__ void setup_w1_kernel(const float* __restrict__ w1)
{
    int i = blockIdx.x * 256 + threadIdx.x;       // 128*9*50 = 57600
    if (i < CIN * 9 * C1) {
        int cin = i / (9 * C1);
        int rem = i - cin * (9 * C1);
        int kk  = rem / C1;
        int oc  = rem - kk * C1;
        float w = w1[oc * (CIN * 9) + cin * 9 + kk];
        g_wdup[i] = make_float2(w, w);
    }
}

// conv1 smem layout (dynamic):
//   s_raw: [2][8][10][40] float  = 25600 B
//   s_w:   [2][8][9][50] float2  = 57600 B
#define C1_RAW_FLOATS (8 * 10 * 40)
#define C1_W_F2       (8 * 9 * 50)
#define C1_SMEM_BYTES (2 * C1_RAW_FLOATS * 4 + 2 * C1_W_F2 * 8)   // 83200

__device__ __forceinline__ void c1_stage(const float* __restrict__ ctrl_chunk,
                                         const float4* __restrict__ wsrc,
                                         int y0, int x0, int tid,
                                         uint32_t raw_dst, uint32_t w_dst)
{
#pragma unroll
    for (int it = 0; it < 4; ++it) {
        int idx = tid + it * 256;
        if (idx < 800) {
            int c = idx / 100, rem = idx - c * 100;
            int r = rem / 10, g = rem - r * 10;
            int y = y0 + r - 1;
            int gx = x0 - 4 + g * 4;
            bool ok = ((unsigned)y < (unsigned)NHW) && ((unsigned)gx <= 124u);
            int soff = ok ? (c * (NHW * NHW) + y * NHW + gx) : 0;
            cp16(raw_dst + ((c * 10 + r) * 40 + g * 4) * 4,
                 ctrl_chunk + soff, ok ? 16 : 0);
        }
    }
#pragma unroll
    for (int it = 0; it < 8; ++it) {
        int idx = tid + it * 256;
        if (idx < 1800)
            cp16(w_dst + idx * 16, wsrc + idx, 16);
    }
}

template<int CNT>
__device__ __forceinline__ void c1_compute(const float* __restrict__ s_raw,
                                           const float2* __restrict__ s_w,
                                           int tx, int base, ull acc[4][7])
{
#pragma unroll 1
    for (int c = 0; c < 8; ++c) {
#pragma unroll
        for (int kx = 0; kx < 3; ++kx) {
            float v[10];
#pragma unroll
            for (int r = 0; r < 10; ++r)
                v[r] = s_raw[(c * 10 + r) * 40 + tx + kx + 3];
            ull pe[5], po[4];
#pragma unroll
            for (int j = 0; j < 5; ++j) pe[j] = pk2(v[2 * j], v[2 * j + 1]);
#pragma unroll
            for (int j = 0; j < 4; ++j) po[j] = pk2(v[2 * j + 1], v[2 * j + 2]);
            const ull* w0p = (const ull*)(s_w + (c * 9 + 0 * 3 + kx) * C1 + base);
            const ull* w1p = (const ull*)(s_w + (c * 9 + 1 * 3 + kx) * C1 + base);
            const ull* w2p = (const ull*)(s_w + (c * 9 + 2 * 3 + kx) * C1 + base);
#pragma unroll
            for (int q = 0; q < CNT; ++q) {
                ull wa = w0p[q];
                fma2(acc[0][q], pe[0], wa); fma2(acc[1][q], pe[1], wa);
                fma2(acc[2][q], pe[2], wa); fma2(acc[3][q], pe[3], wa);
                ull wb = w1p[q];
                fma2(acc[0][q], po[0], wb); fma2(acc[1][q], po[1], wb);
                fma2(acc[2][q], po[2], wb); fma2(acc[3][q], po[3], wb);
                ull wc = w2p[q];
                fma2(acc[0][q], pe[1], wc); fma2(acc[1][q], pe[2], wc);
                fma2(acc[2][q], pe[3], wc); fma2(acc[3][q], pe[4], wc);
            }
        }
    }
}

// ---------------------------------------------------------------------------
// conv1 (exact R7 code): 32x8 tile, 256 thr, cp.async double-buffered.
// ---------------------------------------------------------------------------
__global__ __launch_bounds__(256, 2)
void conv1_kernel(const float* __restrict__ ctrl,
                  const float* __restrict__ b1, const float* __restrict__ gamma,
                  const float* __restrict__ beta, const float* __restrict__ mean,
                  const float* __restrict__ var)
{
    extern __shared__ float sdyn[];
    float*  s_raw = sdyn;
    float2* s_w   = (float2*)(sdyn + 2 * C1_RAW_FLOATS);
    const uint32_t raw_u = smem_u32(s_raw);
    const uint32_t w_u   = smem_u32(s_w);

    const int tid = threadIdx.x;
    const int tx = tid & 31;
    const int cg = tid >> 5;
    const int x0 = blockIdx.x * 32;
    const int y0 = blockIdx.y * 8;
    const int b  = blockIdx.z;

    const int cnt  = (cg < 2) ? 7 : 6;
    const int base = (cg < 2) ? cg * 7 : 14 + (cg - 2) * 6;

    ull acc[4][7];
#pragma unroll
    for (int j = 0; j < 4; ++j)
#pragma unroll
        for (int q = 0; q < 7; ++q) acc[j][q] = 0ULL;

    const float* ctrl_b = ctrl + (size_t)b * CIN * NHW * NHW;

    c1_stage(ctrl_b, (const float4*)(g_wdup), y0, x0, tid, raw_u, w_u);
    cp_commit();

    int buf = 0;
#pragma unroll 1
    for (int k = 0; k < 16; ++k) {
        if (k < 15) {
            int nb = buf ^ 1;
            c1_stage(ctrl_b + (k + 1) * 8 * (NHW * NHW),
                     (const float4*)(g_wdup + (k + 1) * 8 * (9 * C1)),
                     y0, x0, tid,
                     raw_u + nb * (C1_RAW_FLOATS * 4),
                     w_u + nb * (C1_W_F2 * 8));
        }
        cp_commit();
        cp_wait1();
        __syncthreads();

        const float*  rb = s_raw + buf * C1_RAW_FLOATS;
        const float2* wb = s_w + buf * C1_W_F2;
        if (cg < 2) c1_compute<7>(rb, wb, tx, base, acc);
        else        c1_compute<6>(rb, wb, tx, base, acc);
        __syncthreads();
        buf ^= 1;
    }

#pragma unroll
    for (int q = 0; q < 7; ++q) {
        if (q < cnt) {
            int oc = base + q;
            float bb = b1[oc];
            float sc = gamma[oc] * rsqrtf(var[oc] + 1e-5f);
            float bt = beta[oc] - mean[oc] * sc;
            float* hp = g_h + (((size_t)b * C1 + oc) * NHW + y0) * NHW + x0 + tx;
#pragma unroll
            for (int j = 0; j < 4; ++j) {
                float lo, hi;
                upk2(acc[j][q], lo, hi);
                hp[(2 * j) * NHW]     = fmaxf(lo + bb, 0.f) * sc + bt;
                hp[(2 * j + 1) * NHW] = fmaxf(hi + bb, 0.f) * sc + bt;
            }
        }
    }
}

// ---------------------------------------------------------------------------
// conv2 split-K (exact R13 code): grid (4,4,16), z = b + 8*half.
// ---------------------------------------------------------------------------
__global__ __launch_bounds__(256)
void conv2_kernel(const float* __restrict__ w2)
{
    __shared__ float  s_in[5][34][34];
    __shared__ float2 s_w[5][9][9];

    const int tx = threadIdx.x & 31;
    const int rg = threadIdx.x >> 5;
    const int x0 = blockIdx.x * 32;
    const int y0 = blockIdx.y * 32;
    const int b    = blockIdx.z & 7;
    const int half = blockIdx.z >> 3;
    const int chbase = half * 25;

    ull acc[4][9];
#pragma unroll
    for (int r = 0; r < 4; ++r)
#pragma unroll
        for (int q = 0; q < 9; ++q) acc[r][q] = 0ULL;

    for (int kc = 0; kc < 25; kc += 5) {
        const int ch = chbase + kc;
        __syncthreads();
        for (int idx = threadIdx.x; idx < 5 * 34 * 34; idx += 256) {
            int c = idx / 1156, rem = idx - c * 1156;
            int r = rem / 34, cl = rem - r * 34;
            int y = y0 + r - 1, x = x0 + cl - 1;
            float v = 0.f;
            if ((unsigned)y < (unsigned)NHW && (unsigned)x < (unsigned)NHW)
                v = g_h[(((size_t)b * C1 + ch + c) * NHW + y) * NHW + x];
            s_in[c][r][cl] = v;
        }
        for (int idx = threadIdx.x; idx < 5 * 9 * 9; idx += 256) {
            int c = idx / 81, rem = idx - c * 81;
            int kk = rem / 9, q2 = rem - kk * 9;
            s_w[c][kk][q2] = make_float2(
                w2[(2 * q2)     * (C1 * 9) + (ch + c) * 9 + kk],
                w2[(2 * q2 + 1) * (C1 * 9) + (ch + c) * 9 + kk]);
        }
        __syncthreads();

        const int rbase = rg * 4;
#pragma unroll 1
        for (int c = 0; c < 5; ++c) {
#pragma unroll
            for (int kx = 0; kx < 3; ++kx) {
                ull pr[6];
#pragma unroll
                for (int r = 0; r < 6; ++r) {
                    float v = s_in[c][rbase + r][tx + kx];
                    pr[r] = pk2(v, v);
                }
#pragma unroll
                for (int ky = 0; ky < 3; ++ky) {
                    const ull* wrow = (const ull*)&s_w[c][ky * 3 + kx][0];
#pragma unroll
                    for (int q2 = 0; q2 < 9; ++q2) {
                        ull wv = wrow[q2];
                        fma2(acc[0][q2], pr[0 + ky], wv);
                        fma2(acc[1][q2], pr[1 + ky], wv);
                        fma2(acc[2][q2], pr[2 + ky], wv);
                        fma2(acc[3][q2], pr[3 + ky], wv);
                    }
                }
            }
        }
    }

    float* gp = g_part + (size_t)half * (BATCH * C2 * NHW * NHW);
#pragma unroll
    for (int q2 = 0; q2 < 9; ++q2) {
        float* p0 = gp + (((size_t)b * C2 + 2 * q2) * NHW + y0 + rg * 4) * NHW + x0 + tx;
        float* p1 = p0 + (size_t)NHW * NHW;
#pragma unroll
        for (int r = 0; r < 4; ++r) {
            float lo, hi;
            upk2(acc[r][q2], lo, hi);
            p0[r * NHW] = lo;
            p1[r * NHW] = hi;
        }
    }
}

// ---------------------------------------------------------------------------
// combine: g_cond = part0 + part1 + b2[channel], float4-vectorized.
// 8*18*128*128 floats = 589824 float4 groups.
// ---------------------------------------------------------------------------
__global__ __launch_bounds__(256)
void combine_kernel(const float* __restrict__ b2)
{
    int i = blockIdx.x * 256 + threadIdx.x;     // float4 index
    // channel = (i*4 / 16384) % 18
    int ch = (i >> 12) % C2;
    const float4* p0 = (const float4*)g_part + i;
    const float4* p1 = (const float4*)(g_part + (size_t)BATCH * C2 * NHW * NHW) + i;
    float4 a = *p0, b = *p1;
    float bb = b2[ch];
    float4 r;
    r.x = a.x + b.x + bb;
    r.y = a.y + b.y + bb;
    r.z = a.z + b.z + bb;
    r.w = a.w + b.w + bb;
    ((float4*)g_cond)[i] = r;
}

// ---------------------------------------------------------------------------
// dynamic 9-tap cell-strided filter (exact R7 version, 4 px per thread).
// out[b,ch,y,x] = sum_k img[b,ch, y+(j-1)*4, x+(i-1)*4] * cond[b, g*9+k, y/4, x/4]
// ---------------------------------------------------------------------------
__global__ __launch_bounds__(256)
void dynfilt_kernel(const float* __restrict__ img, float* __restrict__ out)
{
    int tid = blockIdx.x * 256 + threadIdx.x;   // 8*6*512*128 threads
    int x4 = tid & 127;
    int y  = (tid >> 7) & 511;
    int bc = tid >> 16;            // b*6 + ch
    int ch = bc % 6;
    int b  = bc / 6;
    int g  = ch / 3;

    const float* wp = g_cond + (((size_t)b * C2 + g * 9) * NHW + (y >> 2)) * NHW + x4;
    float w[9];
#pragma unroll
    for (int k = 0; k < 9; ++k) w[k] = wp[(size_t)k * (NHW * NHW)];

    const float* ip = img + ((size_t)b * 6 + ch) * (HH * WW);
    int x = x4 * 4;
    float4 acc = make_float4(0.f, 0.f, 0.f, 0.f);
#pragma unroll
    for (int i = 0; i < 3; ++i) {
        int xx = x + (i - 1) * 4;
        bool xok = (unsigned)xx < (unsigned)WW;
#pragma unroll
        for (int j = 0; j < 3; ++j) {
            int yy = y + (j - 1) * 4;
            float4 v = make_float4(0.f, 0.f, 0.f, 0.f);
            if (xok && (unsigned)yy < (unsigned)HH)
                v = *(const float4*)(ip + (size_t)yy * WW + xx);
            float wk = w[i * 3 + j];
            acc.x = fmaf(v.x, wk, acc.x);
            acc.y = fmaf(v.y, wk, acc.y);
            acc.z = fmaf(v.z, wk, acc.z);
            acc.w = fmaf(v.w, wk, acc.w);
        }
    }
    *(float4*)(out + (((size_t)b * 6 + ch) * HH + y) * WW + x) = acc;
}

// ---------------------------------------------------------------------------
extern "C" void kernel_launch(void* const* d_in, const int* in_sizes, int n_in,
                              void* d_out, int out_size)
{
    const float* image = (const float*)d_in[0];
    const float* ctrl  = (const float*)d_in[1];
    const float* w1    = (const float*)d_in[2];
    const float* b1    = (const float*)d_in[3];
    const float* gamma = (const float*)d_in[4];
    const float* beta  = (const float*)d_in[5];
    const float* mean  = (const float*)d_in[6];
    const float* var   = (const float*)d_in[7];
    const float* w2    = (const float*)d_in[8];
    const float* b2    = (const float*)d_in[9];
    float* out = (float*)d_out;

    cudaFuncSetAttribute(conv1_kernel,
                         cudaFuncAttributeMaxDynamicSharedMemorySize, C1_SMEM_BYTES);

    setup_w1_kernel<<<(CIN * 9 * C1 + 255) / 256, 256>>>(w1);
    conv1_kernel<<<dim3(4, 16, BATCH), 256, C1_SMEM_BYTES>>>(ctrl, b1, gamma, beta, mean, var);
    conv2_kernel<<<dim3(4, 4, 16), 256>>>(w2);
    combine_kernel<<<(BATCH * C2 * NHW * NHW / 4) / 256, 256>>>(b2);
    dynfilt_kernel<<<(BATCH * 6 * HH * (WW / 4)) / 256, 256>>>(image, out);
}